// round 15
// baseline (speedup 1.0000x reference)
#include <cuda_runtime.h>
#include <cuda_fp16.h>
#include <math.h>
#include <stdint.h>

#define TOKS 8192
#define DM   1024
#define NE   8
#define DFF  4096
#define NASSIGN (TOKS * 2)
#define GATE_BLOCKS (TOKS / 8)

// ------------- scratch (static device memory; no allocations) -------------
// RULE: no g_* symbol may EVER be passed as a kernel <<<>>> argument.
__device__ __align__(256) __half g_h[(size_t)NASSIGN * DFF];     // 128 MB
__device__ float  g_y[(size_t)NASSIGN * DM];                     //  64 MB
__device__ __align__(256) __half g_w1h[(size_t)NE * DM * DFF];   //  64 MB W1^T [e][n][k]
__device__ __align__(256) __half g_w2h[(size_t)NE * DFF * DM];   //  64 MB W2^T [e][n][k]
__device__ __align__(256) __half g_xh[(size_t)TOKS * DM];        //  16 MB
__device__ int    g_rowlist[NASSIGN];
__device__ float  g_wlist[NASSIGN];
__device__ int    g_slot_of[NASSIGN];
__device__ int    g_topi[NASSIGN];
__device__ float  g_topw[NASSIGN];
__device__ int    g_count[NE];
__device__ int    g_fill[NE];
__device__ int    g_off[NE];
__device__ float  g_blockprob[GATE_BLOCKS * NE];

// ----------------------------- helpers --------------------------------
__device__ __forceinline__ void cp16(void* smem, const void* gmem) {
    uint32_t s = (uint32_t)__cvta_generic_to_shared(smem);
    asm volatile("cp.async.cg.shared.global [%0], [%1], 16;" :: "r"(s), "l"(gmem));
}
#define CP_COMMIT() asm volatile("cp.async.commit_group;")
#define CP_WAIT(n)  asm volatile("cp.async.wait_group %0;" :: "n"(n))

__device__ __forceinline__ void mma_fp16(float* c, const uint32_t* a, const uint32_t* b) {
    asm volatile(
        "mma.sync.aligned.m16n8k16.row.col.f32.f16.f16.f32 "
        "{%0,%1,%2,%3}, {%4,%5,%6,%7}, {%8,%9}, {%0,%1,%2,%3};"
        : "+f"(c[0]), "+f"(c[1]), "+f"(c[2]), "+f"(c[3])
        : "r"(a[0]), "r"(a[1]), "r"(a[2]), "r"(a[3]), "r"(b[0]), "r"(b[1]));
}

__device__ __forceinline__ void ldsm_x4(uint32_t& r0, uint32_t& r1,
                                        uint32_t& r2, uint32_t& r3, uint32_t saddr) {
    asm volatile("ldmatrix.sync.aligned.m8n8.x4.shared.b16 {%0,%1,%2,%3}, [%4];"
                 : "=r"(r0), "=r"(r1), "=r"(r2), "=r"(r3) : "r"(saddr));
}

// ---------------------------------------------------------------------------
__global__ void zero_counters() {
    int i = threadIdx.x;
    if (i < NE) { g_count[i] = 0; g_fill[i] = 0; }
}

// W[e][K][N] fp32 -> g_w{1,2}h[e][N][K] fp16; destination resolved in DEVICE code.
template<bool IS_W1>
__global__ __launch_bounds__(256) void transpose_convert(const float* __restrict__ W)
{
    const int K = IS_W1 ? DM : DFF;
    const int N = IS_W1 ? DFF : DM;
    __half* Wt = IS_W1 ? g_w1h : g_w2h;

    __shared__ float t[32][33];
    int e = blockIdx.z;
    int k0 = blockIdx.y * 32, n0 = blockIdx.x * 32;
    const float* src = W + (size_t)e * K * N;
    __half* dst = Wt + (size_t)e * K * N;
    int tx = threadIdx.x & 31, ty = threadIdx.x >> 5;  // 32 x 8
#pragma unroll
    for (int r = 0; r < 4; r++)
        t[ty * 4 + r][tx] = src[(size_t)(k0 + ty * 4 + r) * N + n0 + tx];
    __syncthreads();
#pragma unroll
    for (int r = 0; r < 4; r++)
        dst[(size_t)(n0 + ty * 4 + r) * K + k0 + tx] = __float2half_rn(t[tx][ty * 4 + r]);
}

// One warp per token; 8 warps (8 tokens) per block.
// Fused: also writes the fp16 copy of x (g_xh) during the streaming pass.
__global__ __launch_bounds__(256) void gate_kernel(
    const float* __restrict__ x, const float* __restrict__ Wg)
{
    int warp = threadIdx.x >> 5, lane = threadIdx.x & 31;
    int t = blockIdx.x * 8 + warp;
    __shared__ float probs_sh[8][NE];

    float acc[NE];
#pragma unroll
    for (int e = 0; e < NE; e++) acc[e] = 0.f;
    const float* xr = x + (size_t)t * DM;
    __half* xh = g_xh + (size_t)t * DM;
    for (int i = lane; i < DM; i += 32) {
        float xv = xr[i];
        xh[i] = __float2half_rn(xv);
#pragma unroll
        for (int e = 0; e < NE; e++) acc[e] += xv * Wg[i * NE + e];
    }
#pragma unroll
    for (int off = 16; off; off >>= 1)
#pragma unroll
        for (int e = 0; e < NE; e++)
            acc[e] += __shfl_xor_sync(0xFFFFFFFFu, acc[e], off);

    if (lane == 0) {
        float mx = acc[0];
#pragma unroll
        for (int e = 1; e < NE; e++) mx = fmaxf(mx, acc[e]);
        float p[NE], s = 0.f;
#pragma unroll
        for (int e = 0; e < NE; e++) { p[e] = __expf(acc[e] - mx); s += p[e]; }
        float inv = 1.f / s;
#pragma unroll
        for (int e = 0; e < NE; e++) p[e] *= inv;
        int i0 = 0;
#pragma unroll
        for (int e = 1; e < NE; e++) if (p[e] > p[i0]) i0 = e;
        int i1 = (i0 == 0) ? 1 : 0;
#pragma unroll
        for (int e = 0; e < NE; e++) if (e != i0 && p[e] > p[i1]) i1 = e;
        float v0 = p[i0], v1 = p[i1];
        float s2 = 1.f / (v0 + v1 + 1e-8f);
        g_topi[t * 2 + 0] = i0;  g_topw[t * 2 + 0] = v0 * s2;
        g_topi[t * 2 + 1] = i1;  g_topw[t * 2 + 1] = v1 * s2;
        atomicAdd(&g_count[i0], 1);
        atomicAdd(&g_count[i1], 1);
#pragma unroll
        for (int e = 0; e < NE; e++) probs_sh[warp][e] = p[e];
    }
    __syncthreads();
    if (threadIdx.x < NE) {
        float s = 0.f;
#pragma unroll
        for (int w = 0; w < 8; w++) s += probs_sh[w][threadIdx.x];
        g_blockprob[blockIdx.x * NE + threadIdx.x] = s;
    }
}

__global__ void offsets_kernel() {
    if (threadIdx.x == 0) {
        int o = 0;
        for (int e = 0; e < NE; e++) { g_off[e] = o; o += g_count[e]; }
    }
}

__global__ void build_kernel() {
    int a = blockIdx.x * blockDim.x + threadIdx.x;
    if (a >= NASSIGN) return;
    int e = g_topi[a];
    int pos = atomicAdd(&g_fill[e], 1);
    int slot = g_off[e] + pos;
    g_rowlist[slot] = a >> 1;
    g_wlist[slot] = g_topw[a];
    g_slot_of[a] = slot;
}

// ==================== fp16 tensor-core grouped GEMMs =======================
// 128x128x64 block tile, 256 threads = 8 warps, warp tile 32x64,
// ldmatrix.x4 fragment loads, 2-stage ping-pong (R13-proven control flow).
// BK=64 halves commit/wait/sync per FLOP vs BK=32. 72KB dyn smem, 2 CTAs/SM.

#define BK 64
#define ROW_H 72                 // halves per smem row (64 data + 8 pad)
#define TILE_H (128 * ROW_H)     // 9216 halves per operand tile
#define STAGE_H (2 * TILE_H)     // 18432 halves (A + B)
#define GEMM_SMEM (2 * STAGE_H * 2)   // 73728 B

template<int KDIM, int NDIM, bool IS_G1>
__global__ __launch_bounds__(256, 2) void gemm_fp16()
{
    extern __shared__ __align__(16) __half smem[];

    int e = blockIdx.z;
    int M = g_count[e];
    int m0 = blockIdx.y * 128;
    if (m0 >= M) return;
    int n0 = blockIdx.x * 128;
    int base = g_off[e];
    const __half* Wt = (IS_G1 ? g_w1h : g_w2h) + (size_t)e * KDIM * NDIM;  // [N][K]

    int tid = threadIdx.x;
    int lane = tid & 31, warp = tid >> 5;
    int wm = (warp & 3) * 32;
    int wn = (warp >> 2) * 64;
    int g = lane >> 2, tig = lane & 3;

    // cp.async mapping: 2 threads per row (tid>>1 = row 0..127), each does
    // 4x16B chunks of its 128B half-row (half = tid&1).
    int lrow = tid >> 1, half = tid & 1;
    int r = m0 + lrow; if (r >= M) r = M - 1;
    const __half* aptr = IS_G1 ? (g_xh + (size_t)g_rowlist[base + r] * KDIM)
                               : (g_h + (size_t)(base + r) * KDIM);
    const __half* bptr = Wt + (size_t)(n0 + lrow) * KDIM;

    // ldmatrix per-thread address offsets (halves), invariant across k-tiles.
    int q = lane >> 3, rr = lane & 7;
    int a_off = (wm + (q & 1) * 8 + rr) * ROW_H + (q >> 1) * 8;
    int b_off = (wn + (q >> 1) * 8 + rr) * ROW_H + (q & 1) * 8;
    uint32_t sb = (uint32_t)__cvta_generic_to_shared(smem);

    float acc[2][8][4];
#pragma unroll
    for (int i = 0; i < 2; i++)
#pragma unroll
        for (int j = 0; j < 8; j++)
#pragma unroll
            for (int c = 0; c < 4; c++) acc[i][j][c] = 0.f;

    const int NT = KDIM / BK;

#define LOAD_STAGE(ti, s) do {                                                  \
        __half* ab = smem + (s) * STAGE_H;                                      \
        __half* bb = ab + TILE_H;                                               \
        _Pragma("unroll")                                                       \
        for (int c = 0; c < 4; c++) {                                           \
            int ho = (half * 4 + c) * 8;                                        \
            cp16(ab + lrow * ROW_H + ho, aptr + (ti) * BK + ho);                \
            cp16(bb + lrow * ROW_H + ho, bptr + (ti) * BK + ho);                \
        }                                                                       \
        CP_COMMIT();                                                            \
    } while (0)

    LOAD_STAGE(0, 0);

    for (int kt = 0; kt < NT; kt++) {
        int cur = kt & 1;
        if (kt + 1 < NT) {
            LOAD_STAGE(kt + 1, cur ^ 1);   // safe: last read of nxt fenced by trailing sync
            CP_WAIT(1);
        } else {
            CP_WAIT(0);
        }
        __syncthreads();

        uint32_t abase = sb + (uint32_t)(cur * STAGE_H) * 2;
        uint32_t bbase = abase + TILE_H * 2;
#pragma unroll
        for (int ks = 0; ks < 4; ks++) {
            uint32_t af[2][4];
#pragma unroll
            for (int i = 0; i < 2; i++)
                ldsm_x4(af[i][0], af[i][1], af[i][2], af[i][3],
                        abase + (uint32_t)(a_off + i * 16 * ROW_H + ks * 16) * 2);
            uint32_t bf[8][2];
#pragma unroll
            for (int p = 0; p < 4; p++)
                ldsm_x4(bf[2 * p][0], bf[2 * p][1], bf[2 * p + 1][0], bf[2 * p + 1][1],
                        bbase + (uint32_t)(b_off + p * 16 * ROW_H + ks * 16) * 2);
#pragma unroll
            for (int i = 0; i < 2; i++)
#pragma unroll
                for (int j = 0; j < 8; j++) mma_fp16(acc[i][j], af[i], bf[j]);
        }
        __syncthreads();
    }

    // epilogue
#pragma unroll
    for (int i = 0; i < 2; i++) {
        int r0 = m0 + wm + i * 16 + g;
        int r1 = r0 + 8;
        if (IS_G1) {
#pragma unroll
            for (int j = 0; j < 8; j++) {
                int col = n0 + wn + j * 8 + 2 * tig;
                if (r0 < M) {
                    float v0 = acc[i][j][0], v1 = acc[i][j][1];
                    __half2 o = __floats2half2_rn(
                        0.5f * v0 * (1.0f + erff(v0 * 0.70710678118654752f)),
                        0.5f * v1 * (1.0f + erff(v1 * 0.70710678118654752f)));
                    *(__half2*)(g_h + (size_t)(base + r0) * NDIM + col) = o;
                }
                if (r1 < M) {
                    float v2 = acc[i][j][2], v3 = acc[i][j][3];
                    __half2 o = __floats2half2_rn(
                        0.5f * v2 * (1.0f + erff(v2 * 0.70710678118654752f)),
                        0.5f * v3 * (1.0f + erff(v3 * 0.70710678118654752f)));
                    *(__half2*)(g_h + (size_t)(base + r1) * NDIM + col) = o;
                }
            }
        } else {
            float w0 = (r0 < M) ? g_wlist[base + r0] : 0.f;
            float w1 = (r1 < M) ? g_wlist[base + r1] : 0.f;
#pragma unroll
            for (int j = 0; j < 8; j++) {
                int col = n0 + wn + j * 8 + 2 * tig;
                if (r0 < M) {
                    float2 o = make_float2(w0 * acc[i][j][0], w0 * acc[i][j][1]);
                    *(float2*)(g_y + (size_t)(base + r0) * NDIM + col) = o;
                }
                if (r1 < M) {
                    float2 o = make_float2(w1 * acc[i][j][2], w1 * acc[i][j][3]);
                    *(float2*)(g_y + (size_t)(base + r1) * NDIM + col) = o;
                }
            }
        }
    }
}

// ----------------- combine: out[t] = y[slot0] + y[slot1] -------------------
__global__ void combine_kernel(float* __restrict__ out) {
    int idx = blockIdx.x * blockDim.x + threadIdx.x;
    if (idx >= TOKS * DM / 4) return;
    int t  = idx / (DM / 4);
    int d4 = idx % (DM / 4);
    int s0 = g_slot_of[t * 2 + 0];
    int s1 = g_slot_of[t * 2 + 1];
    float4 a = *(const float4*)(g_y + (size_t)s0 * DM + d4 * 4);
    float4 b = *(const float4*)(g_y + (size_t)s1 * DM + d4 * 4);
    ((float4*)out)[idx] = make_float4(a.x + b.x, a.y + b.y, a.z + b.z, a.w + b.w);
}

// ----------------- load-balance loss ---------------------------------------
__global__ void loss_kernel(float* __restrict__ out, int out_size) {
    __shared__ float sh[256];
    int e = threadIdx.x & 7, part = threadIdx.x >> 3;
    float s = 0.f;
    for (int b = part; b < GATE_BLOCKS; b += 32) s += g_blockprob[b * NE + e];
    sh[threadIdx.x] = s;
    __syncthreads();
    if (threadIdx.x < NE) {
        float rp = 0.f;
        for (int p = 0; p < 32; p++) rp += sh[p * NE + threadIdx.x];
        rp /= (float)TOKS;
        float usage = (float)g_count[threadIdx.x] / (float)NASSIGN;
        sh[threadIdx.x] = rp * usage;
    }
    __syncthreads();
    if (threadIdx.x == 0) {
        float loss = 0.f;
        for (int e2 = 0; e2 < NE; e2++) loss += sh[e2];
        loss *= (float)NE;
        if (out_size > TOKS * DM) out[TOKS * DM] = loss;
    }
}

// ---------------------------------------------------------------------------
extern "C" void kernel_launch(void* const* d_in, const int* in_sizes, int n_in,
                              void* d_out, int out_size)
{
    const float* x  = (const float*)d_in[0];
    const float* Wg = (const float*)d_in[1];
    const float* W1 = (const float*)d_in[2];
    const float* W2 = (const float*)d_in[3];
    float* out = (float*)d_out;

    cudaFuncSetAttribute(gemm_fp16<DM, DFF, true>,
                         cudaFuncAttributeMaxDynamicSharedMemorySize, GEMM_SMEM);
    cudaFuncSetAttribute(gemm_fp16<DFF, DM, false>,
                         cudaFuncAttributeMaxDynamicSharedMemorySize, GEMM_SMEM);

    zero_counters<<<1, 32>>>();
    transpose_convert<true><<<dim3(DFF / 32, DM / 32, NE), 256>>>(W1);
    transpose_convert<false><<<dim3(DM / 32, DFF / 32, NE), 256>>>(W2);
    gate_kernel<<<GATE_BLOCKS, 256>>>(x, Wg);
    offsets_kernel<<<1, 32>>>();
    build_kernel<<<(NASSIGN + 255) / 256, 256>>>();

    gemm_fp16<DM, DFF, true><<<dim3(DFF / 128, NASSIGN / 128, NE), 256, GEMM_SMEM>>>();
    gemm_fp16<DFF, DM, false><<<dim3(DM / 128, NASSIGN / 128, NE), 256, GEMM_SMEM>>>();

    combine_kernel<<<(TOKS * DM / 4 + 255) / 256, 256>>>(out);
    loss_kernel<<<1, 256>>>(out, out_size);
}

// round 16
// speedup vs baseline: 1.3115x; 1.3115x over previous
#include <cuda_runtime.h>
#include <cuda_fp16.h>
#include <math.h>
#include <stdint.h>

#define TOKS 8192
#define DM   1024
#define NE   8
#define DFF  4096
#define NASSIGN (TOKS * 2)
#define GATE_BLOCKS (TOKS / 8)

// ------------- scratch (static device memory; no allocations) -------------
// RULE: no g_* symbol may EVER be passed as a kernel <<<>>> argument.
__device__ __align__(256) __half g_h[(size_t)NASSIGN * DFF];     // 128 MB
__device__ float  g_y[(size_t)NASSIGN * DM];                     //  64 MB
__device__ __align__(256) __half g_w1h[(size_t)NE * DM * DFF];   //  64 MB W1^T [e][n][k]
__device__ __align__(256) __half g_w2h[(size_t)NE * DFF * DM];   //  64 MB W2^T [e][n][k]
__device__ __align__(256) __half g_xh[(size_t)TOKS * DM];        //  16 MB
__device__ int    g_rowlist[NASSIGN];
__device__ float  g_wlist[NASSIGN];
__device__ int    g_slot_of[NASSIGN];
__device__ int    g_topi[NASSIGN];
__device__ float  g_topw[NASSIGN];
__device__ int    g_count[NE];
__device__ int    g_fill[NE];
__device__ int    g_off[NE];
__device__ float  g_blockprob[GATE_BLOCKS * NE];

// ----------------------------- helpers --------------------------------
__device__ __forceinline__ void cp16(void* smem, const void* gmem) {
    uint32_t s = (uint32_t)__cvta_generic_to_shared(smem);
    asm volatile("cp.async.cg.shared.global [%0], [%1], 16;" :: "r"(s), "l"(gmem));
}
#define CP_COMMIT() asm volatile("cp.async.commit_group;")
#define CP_WAIT(n)  asm volatile("cp.async.wait_group %0;" :: "n"(n))

__device__ __forceinline__ void mma_fp16(float* c, const uint32_t* a, const uint32_t* b) {
    asm volatile(
        "mma.sync.aligned.m16n8k16.row.col.f32.f16.f16.f32 "
        "{%0,%1,%2,%3}, {%4,%5,%6,%7}, {%8,%9}, {%0,%1,%2,%3};"
        : "+f"(c[0]), "+f"(c[1]), "+f"(c[2]), "+f"(c[3])
        : "r"(a[0]), "r"(a[1]), "r"(a[2]), "r"(a[3]), "r"(b[0]), "r"(b[1]));
}

__device__ __forceinline__ void ldsm_x4(uint32_t& r0, uint32_t& r1,
                                        uint32_t& r2, uint32_t& r3, uint32_t saddr) {
    asm volatile("ldmatrix.sync.aligned.m8n8.x4.shared.b16 {%0,%1,%2,%3}, [%4];"
                 : "=r"(r0), "=r"(r1), "=r"(r2), "=r"(r3) : "r"(saddr));
}

// ---------------------------------------------------------------------------
__global__ void zero_counters() {
    int i = threadIdx.x;
    if (i < NE) { g_count[i] = 0; g_fill[i] = 0; }
}

// x (fp32) -> g_xh (fp16)
__global__ __launch_bounds__(256) void convert_x(const float* __restrict__ x) {
    size_t i = blockIdx.x * (size_t)blockDim.x + threadIdx.x;
    if (i >= (size_t)TOKS * DM / 4) return;
    float4 v = ((const float4*)x)[i];
    __half2 h0 = __floats2half2_rn(v.x, v.y);
    __half2 h1 = __floats2half2_rn(v.z, v.w);
    uint2 o; o.x = *(uint32_t*)&h0; o.y = *(uint32_t*)&h1;
    ((uint2*)g_xh)[i] = o;
}

// W[e][K][N] fp32 -> g_w{1,2}h[e][N][K] fp16; destination resolved in DEVICE code.
template<bool IS_W1>
__global__ __launch_bounds__(256) void transpose_convert(const float* __restrict__ W)
{
    const int K = IS_W1 ? DM : DFF;
    const int N = IS_W1 ? DFF : DM;
    __half* Wt = IS_W1 ? g_w1h : g_w2h;

    __shared__ float t[32][33];
    int e = blockIdx.z;
    int k0 = blockIdx.y * 32, n0 = blockIdx.x * 32;
    const float* src = W + (size_t)e * K * N;
    __half* dst = Wt + (size_t)e * K * N;
    int tx = threadIdx.x & 31, ty = threadIdx.x >> 5;  // 32 x 8
#pragma unroll
    for (int r = 0; r < 4; r++)
        t[ty * 4 + r][tx] = src[(size_t)(k0 + ty * 4 + r) * N + n0 + tx];
    __syncthreads();
#pragma unroll
    for (int r = 0; r < 4; r++)
        dst[(size_t)(n0 + ty * 4 + r) * K + k0 + tx] = __float2half_rn(t[tx][ty * 4 + r]);
}

// One warp per token; 8 warps (8 tokens) per block.
__global__ __launch_bounds__(256) void gate_kernel(
    const float* __restrict__ x, const float* __restrict__ Wg)
{
    int warp = threadIdx.x >> 5, lane = threadIdx.x & 31;
    int t = blockIdx.x * 8 + warp;
    __shared__ float probs_sh[8][NE];

    float acc[NE];
#pragma unroll
    for (int e = 0; e < NE; e++) acc[e] = 0.f;
    const float* xr = x + (size_t)t * DM;
    for (int i = lane; i < DM; i += 32) {
        float xv = xr[i];
#pragma unroll
        for (int e = 0; e < NE; e++) acc[e] += xv * Wg[i * NE + e];
    }
#pragma unroll
    for (int off = 16; off; off >>= 1)
#pragma unroll
        for (int e = 0; e < NE; e++)
            acc[e] += __shfl_xor_sync(0xFFFFFFFFu, acc[e], off);

    if (lane == 0) {
        float mx = acc[0];
#pragma unroll
        for (int e = 1; e < NE; e++) mx = fmaxf(mx, acc[e]);
        float p[NE], s = 0.f;
#pragma unroll
        for (int e = 0; e < NE; e++) { p[e] = __expf(acc[e] - mx); s += p[e]; }
        float inv = 1.f / s;
#pragma unroll
        for (int e = 0; e < NE; e++) p[e] *= inv;
        int i0 = 0;
#pragma unroll
        for (int e = 1; e < NE; e++) if (p[e] > p[i0]) i0 = e;
        int i1 = (i0 == 0) ? 1 : 0;
#pragma unroll
        for (int e = 0; e < NE; e++) if (e != i0 && p[e] > p[i1]) i1 = e;
        float v0 = p[i0], v1 = p[i1];
        float s2 = 1.f / (v0 + v1 + 1e-8f);
        g_topi[t * 2 + 0] = i0;  g_topw[t * 2 + 0] = v0 * s2;
        g_topi[t * 2 + 1] = i1;  g_topw[t * 2 + 1] = v1 * s2;
        atomicAdd(&g_count[i0], 1);
        atomicAdd(&g_count[i1], 1);
#pragma unroll
        for (int e = 0; e < NE; e++) probs_sh[warp][e] = p[e];
    }
    __syncthreads();
    if (threadIdx.x < NE) {
        float s = 0.f;
#pragma unroll
        for (int w = 0; w < 8; w++) s += probs_sh[w][threadIdx.x];
        g_blockprob[blockIdx.x * NE + threadIdx.x] = s;
    }
}

// build + inlined offsets (each thread computes the 8-entry prefix itself;
// threads 0..7 publish g_off for the GEMM kernels).
__global__ void build_kernel() {
    int a = blockIdx.x * blockDim.x + threadIdx.x;
    if (a >= NASSIGN) return;
    int offs[NE];
    int o = 0;
#pragma unroll
    for (int e = 0; e < NE; e++) { offs[e] = o; o += g_count[e]; }
    if (a < NE) g_off[a] = offs[a];
    int e = g_topi[a];
    int pos = atomicAdd(&g_fill[e], 1);
    int slot = offs[e] + pos;
    g_rowlist[slot] = a >> 1;
    g_wlist[slot] = g_topw[a];
    g_slot_of[a] = slot;
}

// ==================== fp16 tensor-core grouped GEMMs =======================
// R14 (best) config: 128x128x32 block tile, 256 threads = 8 warps, warp tile
// 32x64, ldmatrix.x4 fragment loads, 3-stage cp.async ring with ONE
// __syncthreads per k-tile. 60KB dyn smem, 2 CTAs/SM.

#define BK 32
#define ROW_H 40                 // halves per smem row (32 data + 8 pad)
#define TILE_H (128 * ROW_H)     // halves per operand tile
#define STAGE_H (2 * TILE_H)     // A tile + B tile, halves
#define NST 3
#define GEMM_SMEM (NST * STAGE_H * 2)   // 61440 B

template<int KDIM, int NDIM, bool IS_G1>
__global__ __launch_bounds__(256, 2) void gemm_fp16()
{
    extern __shared__ __align__(16) __half smem[];

    int e = blockIdx.z;
    int M = g_count[e];
    int m0 = blockIdx.y * 128;
    if (m0 >= M) return;
    int n0 = blockIdx.x * 128;
    int base = g_off[e];
    const __half* Wt = (IS_G1 ? g_w1h : g_w2h) + (size_t)e * KDIM * NDIM;  // [N][K]

    int tid = threadIdx.x;
    int lane = tid & 31, warp = tid >> 5;
    int wm = (warp & 3) * 32;
    int wn = (warp >> 2) * 64;
    int g = lane >> 2, tig = lane & 3;

    // cp.async mapping: 4 threads per row, rows (tid>>2) and 64+(tid>>2)
    int lrow = tid >> 2, chunk = tid & 3;     // chunk*8 halves = chunk*16 bytes
    const __half* aptr[2];
    const __half* bptr[2];
#pragma unroll
    for (int it = 0; it < 2; it++) {
        int r = m0 + lrow + it * 64; if (r >= M) r = M - 1;
        aptr[it] = IS_G1 ? (g_xh + (size_t)g_rowlist[base + r] * KDIM)
                         : (g_h + (size_t)(base + r) * KDIM);
        bptr[it] = Wt + (size_t)(n0 + lrow + it * 64) * KDIM;
    }

    // ldmatrix per-thread address offsets (halves), invariant across k-tiles.
    int q = lane >> 3, rr = lane & 7;
    int a_off = (wm + (q & 1) * 8 + rr) * ROW_H + (q >> 1) * 8;
    int b_off = (wn + (q >> 1) * 8 + rr) * ROW_H + (q & 1) * 8;
    uint32_t sb = (uint32_t)__cvta_generic_to_shared(smem);

    float acc[2][8][4];
#pragma unroll
    for (int i = 0; i < 2; i++)
#pragma unroll
        for (int j = 0; j < 8; j++)
#pragma unroll
            for (int c = 0; c < 4; c++) acc[i][j][c] = 0.f;

    const int NT = KDIM / BK;

#define LOAD_STAGE(ti, s) do {                                                  \
        __half* ab = smem + (s) * STAGE_H;                                      \
        __half* bb = ab + TILE_H;                                               \
        _Pragma("unroll")                                                       \
        for (int it = 0; it < 2; it++) {                                        \
            int rw = lrow + it * 64;                                            \
            cp16(ab + rw * ROW_H + chunk * 8, aptr[it] + (ti) * BK + chunk * 8);\
            cp16(bb + rw * ROW_H + chunk * 8, bptr[it] + (ti) * BK + chunk * 8);\
        }                                                                       \
        CP_COMMIT();                                                            \
    } while (0)

    LOAD_STAGE(0, 0);
    LOAD_STAGE(1, 1);

    for (int kt = 0; kt < NT; kt++) {
        int cur = kt % NST;
        if (kt < NT - 1) CP_WAIT(1);
        else             CP_WAIT(0);
        __syncthreads();   // fences reads of stage (kt-1)%NST before overwrite
        if (kt + 2 < NT) LOAD_STAGE(kt + 2, (kt + 2) % NST);

        uint32_t abase = sb + (uint32_t)(cur * STAGE_H) * 2;
        uint32_t bbase = abase + TILE_H * 2;
#pragma unroll
        for (int ks = 0; ks < 2; ks++) {
            uint32_t af[2][4];
#pragma unroll
            for (int i = 0; i < 2; i++)
                ldsm_x4(af[i][0], af[i][1], af[i][2], af[i][3],
                        abase + (uint32_t)(a_off + i * 16 * ROW_H + ks * 16) * 2);
            uint32_t bf[8][2];
#pragma unroll
            for (int p = 0; p < 4; p++)
                ldsm_x4(bf[2 * p][0], bf[2 * p][1], bf[2 * p + 1][0], bf[2 * p + 1][1],
                        bbase + (uint32_t)(b_off + p * 16 * ROW_H + ks * 16) * 2);
#pragma unroll
            for (int i = 0; i < 2; i++)
#pragma unroll
                for (int j = 0; j < 8; j++) mma_fp16(acc[i][j], af[i], bf[j]);
        }
    }

    // epilogue
#pragma unroll
    for (int i = 0; i < 2; i++) {
        int r0 = m0 + wm + i * 16 + g;
        int r1 = r0 + 8;
        if (IS_G1) {
#pragma unroll
            for (int j = 0; j < 8; j++) {
                int col = n0 + wn + j * 8 + 2 * tig;
                if (r0 < M) {
                    float v0 = acc[i][j][0], v1 = acc[i][j][1];
                    __half2 o = __floats2half2_rn(
                        0.5f * v0 * (1.0f + erff(v0 * 0.70710678118654752f)),
                        0.5f * v1 * (1.0f + erff(v1 * 0.70710678118654752f)));
                    *(__half2*)(g_h + (size_t)(base + r0) * NDIM + col) = o;
                }
                if (r1 < M) {
                    float v2 = acc[i][j][2], v3 = acc[i][j][3];
                    __half2 o = __floats2half2_rn(
                        0.5f * v2 * (1.0f + erff(v2 * 0.70710678118654752f)),
                        0.5f * v3 * (1.0f + erff(v3 * 0.70710678118654752f)));
                    *(__half2*)(g_h + (size_t)(base + r1) * NDIM + col) = o;
                }
            }
        } else {
            float w0 = (r0 < M) ? g_wlist[base + r0] : 0.f;
            float w1 = (r1 < M) ? g_wlist[base + r1] : 0.f;
#pragma unroll
            for (int j = 0; j < 8; j++) {
                int col = n0 + wn + j * 8 + 2 * tig;
                if (r0 < M) {
                    float2 o = make_float2(w0 * acc[i][j][0], w0 * acc[i][j][1]);
                    *(float2*)(g_y + (size_t)(base + r0) * NDIM + col) = o;
                }
                if (r1 < M) {
                    float2 o = make_float2(w1 * acc[i][j][2], w1 * acc[i][j][3]);
                    *(float2*)(g_y + (size_t)(base + r1) * NDIM + col) = o;
                }
            }
        }
    }
}

// ----------------- combine: out[t] = y[slot0] + y[slot1] -------------------
__global__ void combine_kernel(float* __restrict__ out) {
    int idx = blockIdx.x * blockDim.x + threadIdx.x;
    if (idx >= TOKS * DM / 4) return;
    int t  = idx / (DM / 4);
    int d4 = idx % (DM / 4);
    int s0 = g_slot_of[t * 2 + 0];
    int s1 = g_slot_of[t * 2 + 1];
    float4 a = *(const float4*)(g_y + (size_t)s0 * DM + d4 * 4);
    float4 b = *(const float4*)(g_y + (size_t)s1 * DM + d4 * 4);
    ((float4*)out)[idx] = make_float4(a.x + b.x, a.y + b.y, a.z + b.z, a.w + b.w);
}

// ----------------- load-balance loss ---------------------------------------
__global__ void loss_kernel(float* __restrict__ out, int out_size) {
    __shared__ float sh[256];
    int e = threadIdx.x & 7, part = threadIdx.x >> 3;
    float s = 0.f;
    for (int b = part; b < GATE_BLOCKS; b += 32) s += g_blockprob[b * NE + e];
    sh[threadIdx.x] = s;
    __syncthreads();
    if (threadIdx.x < NE) {
        float rp = 0.f;
        for (int p = 0; p < 32; p++) rp += sh[p * NE + threadIdx.x];
        rp /= (float)TOKS;
        float usage = (float)g_count[threadIdx.x] / (float)NASSIGN;
        sh[threadIdx.x] = rp * usage;
    }
    __syncthreads();
    if (threadIdx.x == 0) {
        float loss = 0.f;
        for (int e2 = 0; e2 < NE; e2++) loss += sh[e2];
        loss *= (float)NE;
        if (out_size > TOKS * DM) out[TOKS * DM] = loss;
    }
}

// ---------------------------------------------------------------------------
extern "C" void kernel_launch(void* const* d_in, const int* in_sizes, int n_in,
                              void* d_out, int out_size)
{
    const float* x  = (const float*)d_in[0];
    const float* Wg = (const float*)d_in[1];
    const float* W1 = (const float*)d_in[2];
    const float* W2 = (const float*)d_in[3];
    float* out = (float*)d_out;

    cudaFuncSetAttribute(gemm_fp16<DM, DFF, true>,
                         cudaFuncAttributeMaxDynamicSharedMemorySize, GEMM_SMEM);
    cudaFuncSetAttribute(gemm_fp16<DFF, DM, false>,
                         cudaFuncAttributeMaxDynamicSharedMemorySize, GEMM_SMEM);

    // Order chosen so gemm_fp16<...,true> is the 6th launch (ncu -s 5 -c 1
    // profiles it). All dependencies preserved.
    zero_counters<<<1, 32>>>();                                        // 1
    gate_kernel<<<GATE_BLOCKS, 256>>>(x, Wg);                          // 2
    build_kernel<<<(NASSIGN + 255) / 256, 256>>>();                    // 3
    convert_x<<<(TOKS * DM / 4 + 255) / 256, 256>>>(x);                // 4
    transpose_convert<true><<<dim3(DFF / 32, DM / 32, NE), 256>>>(W1); // 5
    gemm_fp16<DM, DFF, true><<<dim3(DFF / 128, NASSIGN / 128, NE), 256, GEMM_SMEM>>>(); // 6
    transpose_convert<false><<<dim3(DM / 32, DFF / 32, NE), 256>>>(W2);// 7
    gemm_fp16<DFF, DM, false><<<dim3(DM / 128, NASSIGN / 128, NE), 256, GEMM_SMEM>>>(); // 8
    combine_kernel<<<(TOKS * DM / 4 + 255) / 256, 256>>>(out);         // 9
    loss_kernel<<<1, 256>>>(out, out_size);                            // 10
}